// round 2
// baseline (speedup 1.0000x reference)
#include <cuda_runtime.h>
#include <math.h>
#include <float.h>

#define D_FEAT 256
#define BATCH  4096

// One CTA per segment. membership is sorted, so segment `seg` occupies a
// contiguous row range [lower_bound(seg), lower_bound(seg+1)).
// 256 threads = one thread per feature column; each thread reduces its
// column (sum + max) in registers over the segment's rows, then writes
// tanh(sum) to out[seg, c] and tanh(max) to out[seg, 256 + c].
__global__ __launch_bounds__(D_FEAT, 8)
void graph_gather_kernel(const float* __restrict__ feat,
                         const int*   __restrict__ mem,
                         int n_atoms,
                         float* __restrict__ out)
{
    const int seg = blockIdx.x;
    __shared__ int s_bounds[2];

    // Two warps do the two binary searches (redundant-free, ~20 LDG each).
    if (threadIdx.x == 0) {
        int lo = 0, hi = n_atoms;
        while (lo < hi) { int mid = (lo + hi) >> 1; if (mem[mid] < seg) lo = mid + 1; else hi = mid; }
        s_bounds[0] = lo;
    } else if (threadIdx.x == 32) {
        int key = seg + 1;
        int lo = 0, hi = n_atoms;
        while (lo < hi) { int mid = (lo + hi) >> 1; if (mem[mid] < key) lo = mid + 1; else hi = mid; }
        s_bounds[1] = lo;
    }
    __syncthreads();

    const int start = s_bounds[0];
    const int end   = s_bounds[1];
    const int cnt   = end - start;
    const int c     = threadIdx.x;

    const float* __restrict__ p = feat + (size_t)start * D_FEAT + c;

    float sum = 0.0f;
    float mx  = -INFINITY;

    int i = 0;
    // Unrolled main loop: 4 independent loads in flight per thread.
    for (; i + 4 <= cnt; i += 4) {
        float a0 = p[(size_t)(i + 0) * D_FEAT];
        float a1 = p[(size_t)(i + 1) * D_FEAT];
        float a2 = p[(size_t)(i + 2) * D_FEAT];
        float a3 = p[(size_t)(i + 3) * D_FEAT];
        sum += a0 + a1 + a2 + a3;
        mx = fmaxf(mx, fmaxf(fmaxf(a0, a1), fmaxf(a2, a3)));
    }
    for (; i < cnt; ++i) {
        float a = p[(size_t)i * D_FEAT];
        sum += a;
        mx = fmaxf(mx, a);
    }

    float* __restrict__ o = out + (size_t)seg * (2 * D_FEAT);
    o[c]          = tanhf(sum);
    o[D_FEAT + c] = tanhf(mx);
}

extern "C" void kernel_launch(void* const* d_in, const int* in_sizes, int n_in,
                              void* d_out, int out_size)
{
    const float* feat = (const float*)d_in[0];   // [N_ATOMS, 256] fp32
    const int*   mem  = (const int*)d_in[1];     // [N_ATOMS] int32, sorted
    float*       out  = (float*)d_out;           // [4096, 512] fp32

    const int n_atoms = in_sizes[1];

    graph_gather_kernel<<<BATCH, D_FEAT>>>(feat, mem, n_atoms, out);
}

// round 3
// speedup vs baseline: 1.0703x; 1.0703x over previous
#include <cuda_runtime.h>
#include <math.h>
#include <float.h>

#define D_FEAT 256
#define BATCH  4096
#define NV     (D_FEAT / 4)   // 64 float4 per row

// Segment boundary table: g_offsets[s] = first row index with membership >= s.
// g_offsets[BATCH] = n_atoms. Filled by boundary_kernel each launch.
__device__ int g_offsets[BATCH + 1];

__global__ void boundary_kernel(const int* __restrict__ mem, int n_atoms)
{
    int i = blockIdx.x * blockDim.x + threadIdx.x;
    if (i >= n_atoms) return;
    int cur  = mem[i];
    int prev = (i == 0) ? -1 : mem[i - 1];
    // membership is sorted; gaps are rare, total writes bounded by BATCH+1.
    for (int s = prev + 1; s <= cur; ++s) g_offsets[s] = i;
    if (i == n_atoms - 1) {
        for (int s = cur + 1; s <= BATCH; ++s) g_offsets[s] = n_atoms;
    }
}

// One CTA per segment. 256 threads: thread t handles column group
// cg = t & 63 (4 consecutive floats) for rows ro, ro+4, ro+8, ...
// where ro = t >> 6. Register float4 sum/max, then an smem reduce
// across the 4 row-groups, then tanh + float4 stores.
__global__ __launch_bounds__(256, 8)
void graph_gather_kernel(const float4* __restrict__ feat,
                         float* __restrict__ out)
{
    const int seg = blockIdx.x;
    const int start = g_offsets[seg];
    const int cnt   = g_offsets[seg + 1] - start;

    const int cg = threadIdx.x & (NV - 1);
    const int ro = threadIdx.x >> 6;

    const float4* __restrict__ p = feat + (size_t)start * NV + cg;

    float4 s = make_float4(0.f, 0.f, 0.f, 0.f);
    float4 m = make_float4(-INFINITY, -INFINITY, -INFINITY, -INFINITY);

    int r = ro;
    // 2-wide unroll: two independent 16B loads in flight per thread.
    for (; r + 4 < cnt; r += 8) {
        float4 a = p[(size_t)r * NV];
        float4 b = p[(size_t)(r + 4) * NV];
        s.x += a.x + b.x;  s.y += a.y + b.y;
        s.z += a.z + b.z;  s.w += a.w + b.w;
        m.x = fmaxf(m.x, fmaxf(a.x, b.x));
        m.y = fmaxf(m.y, fmaxf(a.y, b.y));
        m.z = fmaxf(m.z, fmaxf(a.z, b.z));
        m.w = fmaxf(m.w, fmaxf(a.w, b.w));
    }
    if (r < cnt) {
        float4 a = p[(size_t)r * NV];
        s.x += a.x; s.y += a.y; s.z += a.z; s.w += a.w;
        m.x = fmaxf(m.x, a.x); m.y = fmaxf(m.y, a.y);
        m.z = fmaxf(m.z, a.z); m.w = fmaxf(m.w, a.w);
    }

    __shared__ float4 ssum[256];
    __shared__ float4 smax[256];
    ssum[threadIdx.x] = s;
    smax[threadIdx.x] = m;
    __syncthreads();

    if (threadIdx.x < NV) {
        float4 s0 = ssum[cg],        s1 = ssum[cg + 64];
        float4 s2 = ssum[cg + 128],  s3 = ssum[cg + 192];
        float4 m0 = smax[cg],        m1 = smax[cg + 64];
        float4 m2 = smax[cg + 128],  m3 = smax[cg + 192];

        float4 S, M;
        S.x = (s0.x + s1.x) + (s2.x + s3.x);
        S.y = (s0.y + s1.y) + (s2.y + s3.y);
        S.z = (s0.z + s1.z) + (s2.z + s3.z);
        S.w = (s0.w + s1.w) + (s2.w + s3.w);
        M.x = fmaxf(fmaxf(m0.x, m1.x), fmaxf(m2.x, m3.x));
        M.y = fmaxf(fmaxf(m0.y, m1.y), fmaxf(m2.y, m3.y));
        M.z = fmaxf(fmaxf(m0.z, m1.z), fmaxf(m2.z, m3.z));
        M.w = fmaxf(fmaxf(m0.w, m1.w), fmaxf(m2.w, m3.w));

        float4 tS = make_float4(tanhf(S.x), tanhf(S.y), tanhf(S.z), tanhf(S.w));
        float4 tM = make_float4(tanhf(M.x), tanhf(M.y), tanhf(M.z), tanhf(M.w));

        float4* o = (float4*)out + (size_t)seg * (2 * NV);
        o[cg]      = tS;
        o[NV + cg] = tM;
    }
}

extern "C" void kernel_launch(void* const* d_in, const int* in_sizes, int n_in,
                              void* d_out, int out_size)
{
    const float* feat = (const float*)d_in[0];   // [N_ATOMS, 256] fp32
    const int*   mem  = (const int*)d_in[1];     // [N_ATOMS] int32, sorted
    float*       out  = (float*)d_out;           // [4096, 512] fp32

    const int n_atoms = in_sizes[1];

    boundary_kernel<<<(n_atoms + 255) / 256, 256>>>(mem, n_atoms);
    graph_gather_kernel<<<BATCH, 256>>>((const float4*)feat, out);
}